// round 12
// baseline (speedup 1.0000x reference)
#include <cuda_runtime.h>
#include <cuda_fp16.h>
#include <cstdint>

#define B_    8
#define CIN   320
#define COUT  320
#define H_    64
#define W_    64
#define NPIX  32768     // B*H*W
#define KTOT  2880      // k = tap*320 + ci (tap-major)
#define BM    160
#define BN    128
#define BK    64        // 4 mma k16 steps; tap constant per stage
#define NKI   45
#define NTH   320       // 10 warps: 5 m-pos x 2 n-pos, warp tile 32x64
#define NSTG  3

// __device__ scratch
__device__ __align__(16) __half g_xh[(size_t)NPIX * CIN];      // NHWC fp16 acts (21MB)
__device__ __align__(16) __half g_wh[(size_t)COUT * KTOT];     // weights [o][tap][ci]

// ---------------- helpers ----------------
__device__ __forceinline__ void cp_async16(uint32_t dst, const void* src, int nbytes) {
    asm volatile("cp.async.cg.shared.global [%0], [%1], 16, %2;\n"
                 :: "r"(dst), "l"(src), "r"(nbytes));
}
__device__ __forceinline__ void ldsm_x4(uint32_t* r, uint32_t addr) {
    asm volatile("ldmatrix.sync.aligned.m8n8.x4.shared.b16 {%0,%1,%2,%3}, [%4];"
                 : "=r"(r[0]), "=r"(r[1]), "=r"(r[2]), "=r"(r[3]) : "r"(addr));
}
__device__ __forceinline__ void hmma(float* d, const uint32_t* a, uint32_t b0, uint32_t b1) {
    asm volatile("mma.sync.aligned.m16n8k16.row.col.f32.f16.f16.f32 "
                 "{%0,%1,%2,%3}, {%4,%5,%6,%7}, {%8,%9}, {%0,%1,%2,%3};"
                 : "+f"(d[0]), "+f"(d[1]), "+f"(d[2]), "+f"(d[3])
                 : "r"(a[0]), "r"(a[1]), "r"(a[2]), "r"(a[3]), "r"(b0), "r"(b1));
}
__device__ __forceinline__ uint32_t swz(uint32_t row, uint32_t byte_in_row) {
    return row * 128 + (byte_in_row ^ ((row & 7) << 4));
}

// ---------------- Fused prep (same as R11) ----------------
#define QSTR 165
__global__ void prep_kernel(const float* __restrict__ x,
                            const int* __restrict__ wint,
                            const float* __restrict__ inv_p,
                            const float* __restrict__ zp_p)
{
    __shared__ uint32_t t32[64 * QSTR];
    const int tid = threadIdx.x;

    if (blockIdx.x >= 1024) {
        const int o = blockIdx.x - 1024;
        const int* src = wint + (size_t)o * 2880;
        __half* dst = g_wh + (size_t)o * KTOT;
        #pragma unroll
        for (int i = 0; i < 12; i++) {
            int j = tid + i * 256;
            if (j < 2880) {
                int tap = j / 320;
                int ci  = j - tap * 320;
                dst[j] = __int2half_rn(src[ci * 9 + tap]);
            }
        }
        return;
    }

    const float inv = inv_p[0];
    const float zp  = zp_p[0];
    const int bh   = blockIdx.x >> 1;
    const int half = blockIdx.x & 1;
    const int b    = bh >> 6, h = bh & 63;
    const int ci_base = half * 160;

    const int w  = tid & 63;
    const int cq = tid >> 6;
    const float* xb = x + (((size_t)b * CIN + ci_base) * H_ + h) * W_ + w;
    #pragma unroll
    for (int i = 0; i < 20; i++) {
        int ci0 = i * 8 + cq * 2;
        float va = xb[(size_t)ci0 * H_ * W_];
        float vb = xb[(size_t)(ci0 + 1) * H_ * W_];
        float qa = fminf(fmaxf(rintf(va * inv) + zp, -128.f), 127.f) - zp;
        float qb = fminf(fmaxf(rintf(vb * inv) + zp, -128.f), 127.f) - zp;
        __half2 hq = __floats2half2_rn(qa, qb);
        t32[w * QSTR + (ci0 >> 1)] = *reinterpret_cast<uint32_t*>(&hq);
    }
    __syncthreads();

    uint32_t* gout = reinterpret_cast<uint32_t*>(
        g_xh + ((size_t)bh * W_) * CIN + ci_base);
    #pragma unroll
    for (int i = 0; i < 20; i++) {
        int idx = tid + i * 256;
        int ww  = idx / 80;
        int c   = idx - ww * 80;
        gout[(size_t)ww * (CIN / 2) + c] = t32[ww * QSTR + c];
    }
}

// ---------------- Main fp16 HMMA implicit-GEMM conv ----------------
static constexpr int A_STG = BM * 128;            // 20480
static constexpr int B_STG = BN * 128;            // 16384
static constexpr int STG   = A_STG + B_STG;       // 36864
static constexpr int SMEM_TOTAL = NSTG * STG;     // 110592 (2 CTAs/SM: 221KB)

__global__ __launch_bounds__(NTH, 2)
void conv_hmma_kernel(const float* __restrict__ scale,
                      const float* __restrict__ bias,
                      float* __restrict__ out)
{
    extern __shared__ __align__(128) unsigned char sm[];
    const uint32_t smb = (uint32_t)__cvta_generic_to_shared(sm);

    const int tid  = threadIdx.x;
    const int warp = tid >> 5;             // 0..9
    const int lane = tid & 31;
    const int wm   = (warp >> 1) * 32;     // 0..128
    const int wn   = (warp & 1) * 64;      // 0/64

    const int n0 = blockIdx.x * BN;        // flat pixel base
    const int m0 = blockIdx.y * BM;        // 0/160

    // ---- precomputed load state ----
    // A: 160 rows x 8 vecs = 1280 chunks = 4 per thread
    const __half* aptr[4];
    uint32_t aoff[4];
    #pragma unroll
    for (int t = 0; t < 4; t++) {
        int idx = tid + t * NTH;
        int row = idx >> 3, vec = idx & 7;
        aptr[t] = g_wh + (size_t)(m0 + row) * KTOT + vec * 8;
        aoff[t] = swz(row, vec * 16);
    }
    // B: 128 rows x 8 vecs = 1024 chunks; threads cover 4 rounds (last partial)
    const __half* bptr[4];
    uint32_t boff[4];
    uint32_t bmask[4];   // bit tap set if in-range
    #pragma unroll
    for (int t = 0; t < 4; t++) {
        int idx = tid + t * NTH;
        bmask[t] = 0; bptr[t] = g_xh; boff[t] = 0;
        if (idx < 1024) {
            int row = idx >> 3, vec = idx & 7;
            int n   = n0 + row;
            int h   = (n >> 6) & 63, w = n & 63;
            bptr[t] = g_xh + (size_t)n * CIN + vec * 8;
            boff[t] = A_STG + swz(row, vec * 16);
            uint32_t msk = 0;
            #pragma unroll
            for (int tap = 0; tap < 9; tap++) {
                int kh = tap / 3, kw = tap - kh * 3;
                bool okb = ((unsigned)(h + kh - 1) < (unsigned)H_) &&
                           ((unsigned)(w + kw - 1) < (unsigned)W_);
                msk |= (okb ? 1u : 0u) << tap;
            }
            bmask[t] = msk;
        }
    }

    float acc[2][8][4];
    #pragma unroll
    for (int mt = 0; mt < 2; mt++)
        #pragma unroll
        for (int nt = 0; nt < 8; nt++)
            #pragma unroll
            for (int r = 0; r < 4; r++)
                acc[mt][nt][r] = 0.f;

    auto load_stage = [&](int it, uint32_t base) {
        const int tap = it / 5;
        const int cib = (it - tap * 5) * BK;
        const int kh  = tap / 3;
        const int kw  = tap - kh * 3;
        const int koff = ((kh - 1) * W_ + (kw - 1)) * CIN + cib;  // halfs
        // A (pointers pre-advanced by caller pattern: recompute from it)
        #pragma unroll
        for (int t = 0; t < 4; t++)
            cp_async16(base + aoff[t], aptr[t] + it * BK, 16);
        // B
        #pragma unroll
        for (int t = 0; t < 4; t++) {
            if (tid + t * NTH < 1024) {
                bool okb = (bmask[t] >> tap) & 1u;
                const __half* src = okb ? (bptr[t] + koff) : g_xh;
                cp_async16(base + boff[t], src, okb ? 16 : 0);
            }
        }
        asm volatile("cp.async.commit_group;\n" ::: "memory");
    };

    load_stage(0, smb);
    load_stage(1, smb + STG);

    const uint32_t a_row = wm + (lane & 15);
    const uint32_t b_row = wn + (lane & 15);
    const uint32_t hi16  = (lane >> 4) * 16;

    uint32_t cur = 0;   // stage byte offset rotates 0, STG, 2*STG
    for (int it = 0; it < NKI; it++) {
        if (it + 1 < NKI) asm volatile("cp.async.wait_group 1;\n" ::: "memory");
        else              asm volatile("cp.async.wait_group 0;\n" ::: "memory");
        __syncthreads();
        if (it + 2 < NKI) {
            uint32_t nxt = cur + 2 * STG;
            if (nxt >= NSTG * STG) nxt -= NSTG * STG;
            load_stage(it + 2, smb + nxt);
        }

        const uint32_t Ab = smb + cur;
        const uint32_t Bb = Ab + A_STG;
        #pragma unroll
        for (int ks = 0; ks < 4; ks++) {
            uint32_t a[2][4];
            #pragma unroll
            for (int mt = 0; mt < 2; mt++)
                ldsm_x4(a[mt], Ab + swz(a_row + mt * 16, ks * 32 + hi16));
            #pragma unroll
            for (int p = 0; p < 4; p++) {
                uint32_t bf[4];
                ldsm_x4(bf, Bb + swz(b_row + p * 16, ks * 32 + hi16));
                #pragma unroll
                for (int mt = 0; mt < 2; mt++) {
                    hmma(acc[mt][p * 2 + 0], a[mt], bf[0], bf[2]);
                    hmma(acc[mt][p * 2 + 1], a[mt], bf[1], bf[3]);
                }
            }
        }
        cur += STG;
        if (cur >= NSTG * STG) cur = 0;
    }

    // ---------------- epilogue (direct fragment -> gmem, flat n) ----------------
    #pragma unroll
    for (int mt = 0; mt < 2; mt++) {
        const int o0 = m0 + wm + mt * 16 + (lane >> 2);
        const int o1 = o0 + 8;
        const float sc0 = scale[o0];
        const float sc1 = scale[o1];
        const float bb0 = bias[o0];
        const float bb1 = bias[o1];
        #pragma unroll
        for (int nt = 0; nt < 8; nt++) {
            const int n   = n0 + wn + nt * 8 + (lane & 3) * 2;
            const int b   = n >> 12;
            const int rem = n & 4095;
            float2 v0, v1;
            v0.x = sc0 * acc[mt][nt][0] + bb0;
            v0.y = sc0 * acc[mt][nt][1] + bb0;
            v1.x = sc1 * acc[mt][nt][2] + bb1;
            v1.y = sc1 * acc[mt][nt][3] + bb1;
            size_t p0 = ((size_t)b * COUT + o0) * 4096 + rem;
            size_t p1 = ((size_t)b * COUT + o1) * 4096 + rem;
            *reinterpret_cast<float2*>(out + p0) = v0;
            *reinterpret_cast<float2*>(out + p1) = v1;
        }
    }
}

// ---------------- Launch ----------------
// Inputs: 0:x f32  1:weight_int i32  2:weight_sum (unused)  3:scale f32
//         4:act_scales_inv f32  5:act_zero_points f32  6:bias f32 ; out f32
extern "C" void kernel_launch(void* const* d_in, const int* in_sizes, int n_in,
                              void* d_out, int out_size)
{
    const float* x    = (const float*)d_in[0];
    const int*   wint = (const int*)  d_in[1];
    const float* scl  = (const float*)d_in[3];
    const float* inv  = (const float*)d_in[4];
    const float* zp   = (const float*)d_in[5];
    const float* bias = (const float*)d_in[6];
    float* out = (float*)d_out;

    cudaFuncSetAttribute(conv_hmma_kernel,
                         cudaFuncAttributeMaxDynamicSharedMemorySize, SMEM_TOTAL);

    prep_kernel<<<1344, 256>>>(x, wint, inv, zp);
    dim3 grid(NPIX / BN, COUT / BM);   // (256, 2) = 512 CTAs, 2 per SM
    conv_hmma_kernel<<<grid, NTH, SMEM_TOTAL>>>(scl, bias, out);
}

// round 13
// speedup vs baseline: 1.1144x; 1.1144x over previous
#include <cuda_runtime.h>
#include <cuda_fp16.h>
#include <cstdint>

#define B_    8
#define CIN   320
#define COUT  320
#define H_    64
#define W_    64
#define NPIX  32768     // B*H*W
#define KTOT  2880      // k = tap*320 + ci (tap-major)
#define BM    320
#define BN    128
#define BK    64        // 4 mma k16 steps; tap constant per stage
#define NKI   45
#define NTH   640       // 20 warps: 10 m-pos x 2 n-pos, warp tile 32x64
#define NSTG  4

// __device__ scratch
__device__ __align__(16) __half g_xh[(size_t)NPIX * CIN];      // NHWC fp16 acts (21MB)
__device__ __align__(16) __half g_wh[(size_t)COUT * KTOT];     // weights [o][tap][ci]

// ---------------- helpers ----------------
__device__ __forceinline__ void cp_async16(uint32_t dst, const void* src, int nbytes) {
    asm volatile("cp.async.cg.shared.global [%0], [%1], 16, %2;\n"
                 :: "r"(dst), "l"(src), "r"(nbytes));
}
__device__ __forceinline__ void ldsm_x4(uint32_t* r, uint32_t addr) {
    asm volatile("ldmatrix.sync.aligned.m8n8.x4.shared.b16 {%0,%1,%2,%3}, [%4];"
                 : "=r"(r[0]), "=r"(r[1]), "=r"(r[2]), "=r"(r[3]) : "r"(addr));
}
__device__ __forceinline__ void hmma(float* d, const uint32_t* a, uint32_t b0, uint32_t b1) {
    asm volatile("mma.sync.aligned.m16n8k16.row.col.f32.f16.f16.f32 "
                 "{%0,%1,%2,%3}, {%4,%5,%6,%7}, {%8,%9}, {%0,%1,%2,%3};"
                 : "+f"(d[0]), "+f"(d[1]), "+f"(d[2]), "+f"(d[3])
                 : "r"(a[0]), "r"(a[1]), "r"(a[2]), "r"(a[3]), "r"(b0), "r"(b1));
}
__device__ __forceinline__ uint32_t swz(uint32_t row, uint32_t byte_in_row) {
    return row * 128 + (byte_in_row ^ ((row & 7) << 4));
}

// ---------------- Fused prep (proven in R11) ----------------
#define QSTR 165
__global__ void prep_kernel(const float* __restrict__ x,
                            const int* __restrict__ wint,
                            const float* __restrict__ inv_p,
                            const float* __restrict__ zp_p)
{
    __shared__ uint32_t t32[64 * QSTR];
    const int tid = threadIdx.x;

    if (blockIdx.x >= 1024) {
        const int o = blockIdx.x - 1024;
        const int* src = wint + (size_t)o * 2880;
        __half* dst = g_wh + (size_t)o * KTOT;
        #pragma unroll
        for (int i = 0; i < 12; i++) {
            int j = tid + i * 256;
            if (j < 2880) {
                int tap = j / 320;
                int ci  = j - tap * 320;
                dst[j] = __int2half_rn(src[ci * 9 + tap]);
            }
        }
        return;
    }

    const float inv = inv_p[0];
    const float zp  = zp_p[0];
    const int bh   = blockIdx.x >> 1;
    const int half = blockIdx.x & 1;
    const int b    = bh >> 6, h = bh & 63;
    const int ci_base = half * 160;

    const int w  = tid & 63;
    const int cq = tid >> 6;
    const float* xb = x + (((size_t)b * CIN + ci_base) * H_ + h) * W_ + w;
    #pragma unroll
    for (int i = 0; i < 20; i++) {
        int ci0 = i * 8 + cq * 2;
        float va = xb[(size_t)ci0 * H_ * W_];
        float vb = xb[(size_t)(ci0 + 1) * H_ * W_];
        float qa = fminf(fmaxf(rintf(va * inv) + zp, -128.f), 127.f) - zp;
        float qb = fminf(fmaxf(rintf(vb * inv) + zp, -128.f), 127.f) - zp;
        __half2 hq = __floats2half2_rn(qa, qb);
        t32[w * QSTR + (ci0 >> 1)] = *reinterpret_cast<uint32_t*>(&hq);
    }
    __syncthreads();

    uint32_t* gout = reinterpret_cast<uint32_t*>(
        g_xh + ((size_t)bh * W_) * CIN + ci_base);
    #pragma unroll
    for (int i = 0; i < 20; i++) {
        int idx = tid + i * 256;
        int ww  = idx / 80;
        int c   = idx - ww * 80;
        gout[(size_t)ww * (CIN / 2) + c] = t32[ww * QSTR + c];
    }
}

// ---------------- Main fp16 HMMA implicit-GEMM conv ----------------
static constexpr int A_STG = BM * 128;            // 40960
static constexpr int B_STG = BN * 128;            // 16384
static constexpr int STG   = A_STG + B_STG;       // 57344
static constexpr int SMEM_TOTAL = NSTG * STG;     // 229376 (<= 232448 cap)

__global__ __launch_bounds__(NTH, 1)
void conv_hmma_kernel(const float* __restrict__ scale,
                      const float* __restrict__ bias,
                      float* __restrict__ out)
{
    extern __shared__ __align__(128) unsigned char sm[];
    const uint32_t smb = (uint32_t)__cvta_generic_to_shared(sm);

    const int tid  = threadIdx.x;
    const int warp = tid >> 5;             // 0..19
    const int lane = tid & 31;
    const int wm   = (warp >> 1) * 32;     // 0..288
    const int wn   = (warp & 1) * 64;      // 0/64

    const int n0 = blockIdx.x * BN;        // flat pixel base

    float acc[2][8][4];
    #pragma unroll
    for (int mt = 0; mt < 2; mt++)
        #pragma unroll
        for (int nt = 0; nt < 8; nt++)
            #pragma unroll
            for (int r = 0; r < 4; r++)
                acc[mt][nt][r] = 0.f;

    auto load_stage = [&](int it) {
        const int kb  = it * BK;
        const int tap = kb / 320;
        const int cib = kb - tap * 320;
        const int kh  = tap / 3;
        const int kw  = tap - kh * 3;
        const int dp  = (kh - 1) * W_ + (kw - 1);
        const uint32_t base = smb + (it & (NSTG - 1)) * STG;
        // A: 320 rows x 128B (2560 x 16B)
        #pragma unroll
        for (int t = 0; t < 4; t++) {
            int idx = tid + t * NTH;
            int row = idx >> 3, vec = idx & 7;
            const void* src = g_wh + (size_t)row * KTOT + kb + vec * 8;
            cp_async16(base + swz(row, vec * 16), src, 16);
        }
        // B: 128 n-rows x 128B (1024 x 16B)
        #pragma unroll
        for (int t = 0; t < 2; t++) {
            int idx = tid + t * NTH;
            if (idx < 1024) {
                int row = idx >> 3, vec = idx & 7;
                int n   = n0 + row;
                int rem = n & 4095;
                int h   = rem >> 6, w = rem & 63;
                int ih  = h + kh - 1;
                int iw  = w + kw - 1;
                bool okb = ((unsigned)ih < (unsigned)H_) && ((unsigned)iw < (unsigned)W_);
                size_t p = okb ? (size_t)(n + dp) : 0;
                const void* src = g_xh + p * CIN + cib + vec * 8;
                cp_async16(base + A_STG + swz(row, vec * 16), src, okb ? 16 : 0);
            }
        }
        asm volatile("cp.async.commit_group;\n" ::: "memory");
    };

    load_stage(0);
    load_stage(1);
    load_stage(2);

    const uint32_t a_row = wm + (lane & 15);
    const uint32_t b_row = wn + (lane & 15);
    const uint32_t hi16  = (lane >> 4) * 16;

    for (int it = 0; it < NKI; it++) {
        if (it + 2 < NKI)      asm volatile("cp.async.wait_group 2;\n" ::: "memory");
        else if (it + 1 < NKI) asm volatile("cp.async.wait_group 1;\n" ::: "memory");
        else                   asm volatile("cp.async.wait_group 0;\n" ::: "memory");
        __syncthreads();
        if (it + 3 < NKI) load_stage(it + 3);

        const uint32_t Ab = smb + (it & (NSTG - 1)) * STG;
        const uint32_t Bb = Ab + A_STG;
        #pragma unroll
        for (int ks = 0; ks < 4; ks++) {
            uint32_t a[2][4];
            #pragma unroll
            for (int mt = 0; mt < 2; mt++)
                ldsm_x4(a[mt], Ab + swz(a_row + mt * 16, ks * 32 + hi16));
            #pragma unroll
            for (int p = 0; p < 4; p++) {
                uint32_t bf[4];
                ldsm_x4(bf, Bb + swz(b_row + p * 16, ks * 32 + hi16));
                #pragma unroll
                for (int mt = 0; mt < 2; mt++) {
                    hmma(acc[mt][p * 2 + 0], a[mt], bf[0], bf[2]);
                    hmma(acc[mt][p * 2 + 1], a[mt], bf[1], bf[3]);
                }
            }
        }
    }

    // ---------------- epilogue (direct fragment -> gmem, flat n) ----------------
    #pragma unroll
    for (int mt = 0; mt < 2; mt++) {
        const int o0 = wm + mt * 16 + (lane >> 2);
        const int o1 = o0 + 8;
        const float sc0 = scale[o0];
        const float sc1 = scale[o1];
        const float bb0 = bias[o0];
        const float bb1 = bias[o1];
        #pragma unroll
        for (int nt = 0; nt < 8; nt++) {
            const int n   = n0 + wn + nt * 8 + (lane & 3) * 2;
            const int b   = n >> 12;
            const int rem = n & 4095;
            float2 v0, v1;
            v0.x = sc0 * acc[mt][nt][0] + bb0;
            v0.y = sc0 * acc[mt][nt][1] + bb0;
            v1.x = sc1 * acc[mt][nt][2] + bb1;
            v1.y = sc1 * acc[mt][nt][3] + bb1;
            size_t p0 = ((size_t)b * COUT + o0) * 4096 + rem;
            size_t p1 = ((size_t)b * COUT + o1) * 4096 + rem;
            *reinterpret_cast<float2*>(out + p0) = v0;
            *reinterpret_cast<float2*>(out + p1) = v1;
        }
    }
}

// ---------------- Launch ----------------
// Inputs: 0:x f32  1:weight_int i32  2:weight_sum (unused)  3:scale f32
//         4:act_scales_inv f32  5:act_zero_points f32  6:bias f32 ; out f32
extern "C" void kernel_launch(void* const* d_in, const int* in_sizes, int n_in,
                              void* d_out, int out_size)
{
    const float* x    = (const float*)d_in[0];
    const int*   wint = (const int*)  d_in[1];
    const float* scl  = (const float*)d_in[3];
    const float* inv  = (const float*)d_in[4];
    const float* zp   = (const float*)d_in[5];
    const float* bias = (const float*)d_in[6];
    float* out = (float*)d_out;

    cudaFuncSetAttribute(conv_hmma_kernel,
                         cudaFuncAttributeMaxDynamicSharedMemorySize, SMEM_TOTAL);

    prep_kernel<<<1344, 256>>>(x, wint, inv, zp);
    conv_hmma_kernel<<<NPIX / BN, NTH, SMEM_TOTAL>>>(scl, bias, out);
}

// round 15
// speedup vs baseline: 1.1384x; 1.0215x over previous
#include <cuda_runtime.h>
#include <cuda_fp16.h>
#include <cstdint>

#define B_    8
#define CIN   320
#define COUT  320
#define H_    64
#define W_    64
#define NPIX  32768     // B*H*W
#define KTOT  2880      // k = tap*320 + ci (tap-major)
#define BM    320
#define BN    128
#define BK    64        // 4 mma k16 steps; tap constant per stage
#define NKI   45
#define NTH   640       // 20 warps: 10 m-pos x 2 n-pos, warp tile 32x64
#define NSTG  4

static constexpr int A_STG = BM * 128;            // 40960 bytes (pre-swizzled image)
static constexpr int B_STG = BN * 128;            // 16384
static constexpr int STG   = A_STG + B_STG;       // 57344
static constexpr int MBAR_OFF = NSTG * STG;       // 229376
static constexpr int SMEM_TOTAL = MBAR_OFF + 64;  // 229440 (< 232448 cap)

// __device__ scratch
__device__ __align__(16)  __half  g_xh[(size_t)NPIX * CIN];          // NHWC fp16 acts
__device__ __align__(128) unsigned char g_wA[(size_t)NKI * A_STG];   // per-stage swizzled A images

// ---------------- helpers ----------------
__device__ __forceinline__ void cp_async16(uint32_t dst, const void* src, int nbytes) {
    asm volatile("cp.async.cg.shared.global [%0], [%1], 16, %2;\n"
                 :: "r"(dst), "l"(src), "r"(nbytes));
}
__device__ __forceinline__ void ldsm_x4(uint32_t* r, uint32_t addr) {
    asm volatile("ldmatrix.sync.aligned.m8n8.x4.shared.b16 {%0,%1,%2,%3}, [%4];"
                 : "=r"(r[0]), "=r"(r[1]), "=r"(r[2]), "=r"(r[3]) : "r"(addr));
}
__device__ __forceinline__ void hmma(float* d, const uint32_t* a, uint32_t b0, uint32_t b1) {
    asm volatile("mma.sync.aligned.m16n8k16.row.col.f32.f16.f16.f32 "
                 "{%0,%1,%2,%3}, {%4,%5,%6,%7}, {%8,%9}, {%0,%1,%2,%3};"
                 : "+f"(d[0]), "+f"(d[1]), "+f"(d[2]), "+f"(d[3])
                 : "r"(a[0]), "r"(a[1]), "r"(a[2]), "r"(a[3]), "r"(b0), "r"(b1));
}
__device__ __forceinline__ uint32_t swz(uint32_t row, uint32_t byte_in_row) {
    return row * 128 + (byte_in_row ^ ((row & 7) << 4));
}
__device__ __forceinline__ void mbar_init(uint32_t m, uint32_t cnt) {
    asm volatile("mbarrier.init.shared.b64 [%0], %1;" :: "r"(m), "r"(cnt) : "memory");
}
__device__ __forceinline__ void mbar_expect_tx(uint32_t m, uint32_t bytes) {
    asm volatile("mbarrier.arrive.expect_tx.shared.b64 _, [%0], %1;"
                 :: "r"(m), "r"(bytes) : "memory");
}
__device__ __forceinline__ void mbar_wait(uint32_t m, uint32_t parity) {
    asm volatile("{\n\t"
                 ".reg .pred P1;\n\t"
                 "WL_%=:\n\t"
                 "mbarrier.try_wait.parity.acquire.cta.shared::cta.b64 P1, [%0], %1, 0x989680;\n\t"
                 "@P1 bra WD_%=;\n\t"
                 "bra WL_%=;\n\t"
                 "WD_%=:\n\t"
                 "}" :: "r"(m), "r"(parity) : "memory");
}
__device__ __forceinline__ void bulk_copy(uint32_t dst, const void* src, uint32_t bytes, uint32_t mbar) {
    asm volatile("cp.async.bulk.shared::cta.global.mbarrier::complete_tx::bytes "
                 "[%0], [%1], %2, [%3];"
                 :: "r"(dst), "l"(src), "r"(bytes), "r"(mbar) : "memory");
}

// ---------------- Fused prep: quantize->NHWC + weight stage-image build ----------------
#define QSTR 165
__global__ void prep_kernel(const float* __restrict__ x,
                            const int* __restrict__ wint,
                            const float* __restrict__ inv_p,
                            const float* __restrict__ zp_p)
{
    __shared__ uint32_t t32[64 * QSTR];
    const int tid = threadIdx.x;

    if (blockIdx.x >= 1024) {
        // ---- weight image build: one o (row) per block ----
        const int o = blockIdx.x - 1024;
        const int* src = wint + (size_t)o * 2880;
        // 45 stages x 8 vecs = 360 uint4 chunks per row
        for (int idx = tid; idx < 360; idx += 256) {
            int it  = idx >> 3;
            int vec = idx & 7;
            int tap = it / 5;
            int cib = (it - tap * 5) * 64 + vec * 8;
            __half hv[8];
            #pragma unroll
            for (int e = 0; e < 8; e++)
                hv[e] = __int2half_rn(src[(cib + e) * 9 + tap]);
            *reinterpret_cast<uint4*>(
                g_wA + (size_t)it * A_STG + swz(o, vec * 16)) =
                *reinterpret_cast<const uint4*>(hv);
        }
        return;
    }

    // ---- quantize: (b,h) row, one 160-ci half ----
    const float inv = inv_p[0];
    const float zp  = zp_p[0];
    const int bh   = blockIdx.x >> 1;
    const int half = blockIdx.x & 1;
    const int b    = bh >> 6, h = bh & 63;
    const int ci_base = half * 160;

    const int w  = tid & 63;
    const int cq = tid >> 6;
    const float* xb = x + (((size_t)b * CIN + ci_base) * H_ + h) * W_ + w;
    #pragma unroll
    for (int i = 0; i < 20; i++) {
        int ci0 = i * 8 + cq * 2;
        float va = xb[(size_t)ci0 * H_ * W_];
        float vb = xb[(size_t)(ci0 + 1) * H_ * W_];
        float qa = fminf(fmaxf(rintf(va * inv) + zp, -128.f), 127.f) - zp;
        float qb = fminf(fmaxf(rintf(vb * inv) + zp, -128.f), 127.f) - zp;
        __half2 hq = __floats2half2_rn(qa, qb);
        t32[w * QSTR + (ci0 >> 1)] = *reinterpret_cast<uint32_t*>(&hq);
    }
    __syncthreads();

    uint32_t* gout = reinterpret_cast<uint32_t*>(
        g_xh + ((size_t)bh * W_) * CIN + ci_base);
    #pragma unroll
    for (int i = 0; i < 20; i++) {
        int idx = tid + i * 256;
        int ww  = idx / 80;
        int c   = idx - ww * 80;
        gout[(size_t)ww * (CIN / 2) + c] = t32[ww * QSTR + c];
    }
}

// ---------------- Main fp16 HMMA implicit-GEMM conv ----------------
__global__ __launch_bounds__(NTH, 1)
void conv_hmma_kernel(const float* __restrict__ scale,
                      const float* __restrict__ bias,
                      float* __restrict__ out)
{
    extern __shared__ __align__(128) unsigned char sm[];
    const uint32_t smb = (uint32_t)__cvta_generic_to_shared(sm);

    const int tid  = threadIdx.x;
    const int warp = tid >> 5;             // 0..19
    const int lane = tid & 31;
    const int wm   = (warp >> 1) * 32;     // 0..288
    const int wn   = (warp & 1) * 64;      // 0/64

    const int n0 = blockIdx.x * BN;        // flat pixel base

    // mbarrier init (one per stage)
    if (tid == 0) {
        #pragma unroll
        for (int s = 0; s < NSTG; s++)
            mbar_init(smb + MBAR_OFF + s * 8, 1);
    }
    __syncthreads();

    float acc[2][8][4];
    #pragma unroll
    for (int mt = 0; mt < 2; mt++)
        #pragma unroll
        for (int nt = 0; nt < 8; nt++)
            #pragma unroll
            for (int r = 0; r < 4; r++)
                acc[mt][nt][r] = 0.f;

    // A stage load: single bulk copy of the pre-swizzled image
    auto load_A = [&](int it) {
        if (tid == 0) {
            uint32_t mbar = smb + MBAR_OFF + (it & (NSTG - 1)) * 8;
            mbar_expect_tx(mbar, A_STG);
            bulk_copy(smb + (it & (NSTG - 1)) * STG,
                      g_wA + (size_t)it * A_STG, A_STG, mbar);
        }
    };
    // B stage load: 1024 x 16B cp.async
    auto load_B = [&](int it) {
        const int tap = it / 5;
        const int cib = (it - tap * 5) * BK;
        const int kh  = tap / 3;
        const int kw  = tap - kh * 3;
        const int dp  = (kh - 1) * W_ + (kw - 1);
        const uint32_t base = smb + (it & (NSTG - 1)) * STG + A_STG;
        #pragma unroll
        for (int t = 0; t < 2; t++) {
            int idx = tid + t * NTH;
            if (idx < 1024) {
                int row = idx >> 3, vec = idx & 7;
                int n   = n0 + row;
                int rem = n & 4095;
                int h   = rem >> 6, w = rem & 63;
                int ih  = h + kh - 1;
                int iw  = w + kw - 1;
                bool okb = ((unsigned)ih < (unsigned)H_) && ((unsigned)iw < (unsigned)W_);
                size_t p = okb ? (size_t)(n + dp) : 0;
                const void* src = g_xh + p * CIN + cib + vec * 8;
                cp_async16(base + swz(row, vec * 16), src, okb ? 16 : 0);
            }
        }
        asm volatile("cp.async.commit_group;\n" ::: "memory");
    };

    load_A(0); load_B(0);
    load_A(1); load_B(1);
    load_A(2); load_B(2);

    const uint32_t a_row = wm + (lane & 15);
    const uint32_t b_row = wn + (lane & 15);
    const uint32_t hi16  = (lane >> 4) * 16;

    for (int it = 0; it < NKI; it++) {
        // wait B (cp.async groups) and A (mbarrier)
        if (it + 2 < NKI)      asm volatile("cp.async.wait_group 2;\n" ::: "memory");
        else if (it + 1 < NKI) asm volatile("cp.async.wait_group 1;\n" ::: "memory");
        else                   asm volatile("cp.async.wait_group 0;\n" ::: "memory");
        mbar_wait(smb + MBAR_OFF + (it & (NSTG - 1)) * 8, (it >> 2) & 1);
        __syncthreads();
        if (it + 3 < NKI) { load_A(it + 3); load_B(it + 3); }

        const uint32_t Ab = smb + (it & (NSTG - 1)) * STG;
        const uint32_t Bb = Ab + A_STG;
        #pragma unroll
        for (int ks = 0; ks < 4; ks++) {
            uint32_t a[2][4];
            #pragma unroll
            for (int mt = 0; mt < 2; mt++)
                ldsm_x4(a[mt], Ab + swz(a_row + mt * 16, ks * 32 + hi16));
            #pragma unroll
            for (int p = 0; p < 4; p++) {
                uint32_t bf[4];
                ldsm_x4(bf, Bb + swz(b_row + p * 16, ks * 32 + hi16));
                #pragma unroll
                for (int mt = 0; mt < 2; mt++) {
                    hmma(acc[mt][p * 2 + 0], a[mt], bf[0], bf[2]);
                    hmma(acc[mt][p * 2 + 1], a[mt], bf[1], bf[3]);
                }
            }
        }
    }

    // ---------------- epilogue (direct fragment -> gmem, flat n) ----------------
    #pragma unroll
    for (int mt = 0; mt < 2; mt++) {
        const int o0 = wm + mt * 16 + (lane >> 2);
        const int o1 = o0 + 8;
        const float sc0 = scale[o0];
        const float sc1 = scale[o1];
        const float bb0 = bias[o0];
        const float bb1 = bias[o1];
        #pragma unroll
        for (int nt = 0; nt < 8; nt++) {
            const int n   = n0 + wn + nt * 8 + (lane & 3) * 2;
            const int b   = n >> 12;
            const int rem = n & 4095;
            float2 v0, v1;
            v0.x = sc0 * acc[mt][nt][0] + bb0;
            v0.y = sc0 * acc[mt][nt][1] + bb0;
            v1.x = sc1 * acc[mt][nt][2] + bb1;
            v1.y = sc1 * acc[mt][nt][3] + bb1;
            size_t p0 = ((size_t)b * COUT + o0) * 4096 + rem;
            size_t p1 = ((size_t)b * COUT + o1) * 4096 + rem;
            *reinterpret_cast<float2*>(out + p0) = v0;
            *reinterpret_cast<float2*>(out + p1) = v1;
        }
    }
}

// ---------------- Launch ----------------
// Inputs: 0:x f32  1:weight_int i32  2:weight_sum (unused)  3:scale f32
//         4:act_scales_inv f32  5:act_zero_points f32  6:bias f32 ; out f32
extern "C" void kernel_launch(void* const* d_in, const int* in_sizes, int n_in,
                              void* d_out, int out_size)
{
    const float* x    = (const float*)d_in[0];
    const int*   wint = (const int*)  d_in[1];
    const float* scl  = (const float*)d_in[3];
    const float* inv  = (const float*)d_in[4];
    const float* zp   = (const float*)d_in[5];
    const float* bias = (const float*)d_in[6];
    float* out = (float*)d_out;

    cudaFuncSetAttribute(conv_hmma_kernel,
                         cudaFuncAttributeMaxDynamicSharedMemorySize, SMEM_TOTAL);

    prep_kernel<<<1344, 256>>>(x, wint, inv, zp);
    conv_hmma_kernel<<<NPIX / BN, NTH, SMEM_TOTAL>>>(scl, bias, out);
}